// round 1
// baseline (speedup 1.0000x reference)
#include <cuda_runtime.h>
#include <cuda_bf16.h>
#include <math.h>

// Problem constants
#define BB 40      // batch
#define TT 20      // time
#define FEA 200
#define HH 1024
#define OUTD 1095
#define LL 12
#define ROWS (BB*TT)   // 800

// Scratch (device globals; no allocation allowed)
__device__ float g_h[2][ROWS * HH];     // ping-pong hidden activations, time-major [T,B,H]
__device__ float g_U[ROWS * 3 * HH];    // SRU pre-activations per layer
__device__ float g_cdump[BB * HH];      // sink for c_last if out buffer too small

// ---------------------------------------------------------------------------
// Generic tiled SGEMM: C[M,N] = A[M,K] * B[K,N] (+bias) (+relu) (+row remap)
// 128x128 tile, BK=16, 256 threads, 8x8 per-thread microtile.
// flags: bit0 bias, bit1 relu, bits[2:4] remap mode:
//   0: out_row = row
//   1: row is (b*T+t) -> out_row = t*B+b   (dense1: batch-major in, time-major out)
//   2: row is (t*B+b) -> out_row = b*T+t   (dense4: time-major in, batch-major out)
// ---------------------------------------------------------------------------
#define BM 128
#define BN 128
#define BK 16
#define TM 8
#define TN 8

__global__ __launch_bounds__(256, 2)
void sgemm_kernel(const float* __restrict__ A, const float* __restrict__ B,
                  const float* __restrict__ bias, float* __restrict__ C,
                  int M, int N, int K, int flags)
{
    __shared__ float As[BK][BM];
    __shared__ float Bs[BK][BN];

    const int tid = threadIdx.x;
    const int tx = tid % (BN / TN);   // 0..15
    const int ty = tid / (BN / TN);   // 0..15
    const int m0 = blockIdx.y * BM;
    const int n0 = blockIdx.x * BN;

    float acc[TM][TN];
#pragma unroll
    for (int i = 0; i < TM; i++)
#pragma unroll
        for (int j = 0; j < TN; j++) acc[i][j] = 0.0f;

    for (int kk = 0; kk < K; kk += BK) {
        // Load A tile: 128x16 = 2048 elems, 8 per thread, coalesced along K
#pragma unroll
        for (int i = 0; i < 8; i++) {
            int idx = tid + i * 256;           // 0..2047
            int kIdx = idx % BK;
            int mIdx = idx / BK;
            int gm = m0 + mIdx;
            int gk = kk + kIdx;
            As[kIdx][mIdx] = (gm < M && gk < K) ? A[(size_t)gm * K + gk] : 0.0f;
        }
        // Load B tile: 16x128 = 2048 elems, coalesced along N
#pragma unroll
        for (int i = 0; i < 8; i++) {
            int idx = tid + i * 256;
            int nIdx = idx % BN;
            int kIdx = idx / BN;
            int gk = kk + kIdx;
            int gn = n0 + nIdx;
            Bs[kIdx][nIdx] = (gk < K && gn < N) ? B[(size_t)gk * N + gn] : 0.0f;
        }
        __syncthreads();

#pragma unroll
        for (int k = 0; k < BK; k++) {
            float a[TM], b[TN];
            const float4* As4 = reinterpret_cast<const float4*>(&As[k][ty * TM]);
            float4 av0 = As4[0], av1 = As4[1];
            a[0]=av0.x; a[1]=av0.y; a[2]=av0.z; a[3]=av0.w;
            a[4]=av1.x; a[5]=av1.y; a[6]=av1.z; a[7]=av1.w;
            const float4* Bs4 = reinterpret_cast<const float4*>(&Bs[k][tx * TN]);
            float4 bv0 = Bs4[0], bv1 = Bs4[1];
            b[0]=bv0.x; b[1]=bv0.y; b[2]=bv0.z; b[3]=bv0.w;
            b[4]=bv1.x; b[5]=bv1.y; b[6]=bv1.z; b[7]=bv1.w;
#pragma unroll
            for (int i = 0; i < TM; i++)
#pragma unroll
                for (int j = 0; j < TN; j++)
                    acc[i][j] = fmaf(a[i], b[j], acc[i][j]);
        }
        __syncthreads();
    }

    const bool has_bias = flags & 1;
    const bool do_relu  = flags & 2;
    const int remap     = (flags >> 2) & 3;

#pragma unroll
    for (int i = 0; i < TM; i++) {
        int row = m0 + ty * TM + i;
        if (row >= M) continue;
        int out_row = row;
        if (remap == 1) { int t = row % TT, b = row / TT; out_row = t * BB + b; }
        else if (remap == 2) { int t = row / BB, b = row % BB; out_row = b * TT + t; }
#pragma unroll
        for (int j = 0; j < TN; j++) {
            int col = n0 + tx * TN + j;
            if (col >= N) continue;
            float v = acc[i][j];
            if (has_bias) v += bias[col];
            if (do_relu) v = fmaxf(v, 0.0f);
            C[(size_t)out_row * N + col] = v;
        }
    }
}

// ---------------------------------------------------------------------------
// SRU recurrence + highway for one layer.
// U: [T*B, 3H] time-major rows (x_tilde | uf | ur)
// h_in: [T*B, H] layer input (time-major), c0: [B,H], b_lay: [2H] (bf|br)
// h_out: [T*B, H], c_out: [B,H]
// ---------------------------------------------------------------------------
__global__ void sru_scan_kernel(const float* __restrict__ U,
                                const float* __restrict__ h_in,
                                const float* __restrict__ c0,
                                const float* __restrict__ b_lay,
                                float* __restrict__ h_out,
                                float* __restrict__ c_out)
{
    int idx = blockIdx.x * blockDim.x + threadIdx.x;   // [0, B*H)
    if (idx >= BB * HH) return;
    int b = idx / HH;
    int j = idx % HH;

    float c = c0[(size_t)b * HH + j];
    float bf = b_lay[j];
    float br = b_lay[HH + j];

#pragma unroll 4
    for (int t = 0; t < TT; t++) {
        int r = t * BB + b;
        size_t base = (size_t)r * (3 * HH);
        float xt = U[base + j];
        float uf = U[base + HH + j];
        float ur = U[base + 2 * HH + j];
        float f  = 1.0f / (1.0f + expf(-(uf + bf)));
        float rr = 1.0f / (1.0f + expf(-(ur + br)));
        c = f * c + (1.0f - f) * xt;
        float hprev = h_in[(size_t)r * HH + j];
        h_out[(size_t)r * HH + j] = rr * tanhf(c) + (1.0f - rr) * hprev;
    }
    c_out[(size_t)b * HH + j] = c;
}

// ---------------------------------------------------------------------------

static inline dim3 gemm_grid(int M, int N) {
    return dim3((N + BN - 1) / BN, (M + BM - 1) / BM);
}

extern "C" void kernel_launch(void* const* d_in, const int* in_sizes, int n_in,
                              void* d_out, int out_size)
{
    const float* x      = (const float*)d_in[0];   // [B,T,FEA]
    const float* hidden = (const float*)d_in[1];   // [L,B,H]
    const float* W1     = (const float*)d_in[2];   // [FEA,H]
    const float* b1     = (const float*)d_in[3];   // [H]
    const float* sruW   = (const float*)d_in[4];   // [L,H,3H]
    const float* srub   = (const float*)d_in[5];   // [L,2H]
    const float* W3     = (const float*)d_in[6];   // [H,H]
    const float* b3     = (const float*)d_in[7];   // [H]
    const float* W4     = (const float*)d_in[8];   // [H,OUT]
    const float* b4     = (const float*)d_in[9];   // [OUT]
    float* out = (float*)d_out;

    float* hbuf0; float* hbuf1; float* Ubuf; float* cdump;
    cudaGetSymbolAddress((void**)&hbuf0, g_h);
    hbuf1 = hbuf0 + (size_t)ROWS * HH;
    cudaGetSymbolAddress((void**)&Ubuf, g_U);
    cudaGetSymbolAddress((void**)&cdump, g_cdump);

    const int total_out = ROWS * OUTD + LL * BB * HH;  // 876000 + 491520
    const bool write_hidden = (out_size >= total_out);
    float* hid_out_base = write_hidden ? (out + (size_t)ROWS * OUTD) : nullptr;

    // 1) dense1: x[b*T+t, FEA] @ W1 -> h0 time-major [t*B+b, H]
    sgemm_kernel<<<gemm_grid(ROWS, HH), 256>>>(x, W1, b1, hbuf0,
                                               ROWS, HH, FEA, /*bias|remap1*/ 1 | (1 << 2));

    // 2) SRU layers
    float* bufs[2] = {hbuf0, hbuf1};
    for (int l = 0; l < LL; l++) {
        const float* hin  = bufs[l & 1];
        float*       hout = bufs[(l + 1) & 1];
        const float* Wl = sruW + (size_t)l * HH * 3 * HH;
        const float* bl = srub + (size_t)l * 2 * HH;
        const float* c0 = hidden + (size_t)l * BB * HH;
        float* cout = write_hidden ? (hid_out_base + (size_t)l * BB * HH) : cdump;

        sgemm_kernel<<<gemm_grid(ROWS, 3 * HH), 256>>>(hin, Wl, nullptr, Ubuf,
                                                       ROWS, 3 * HH, HH, 0);
        sru_scan_kernel<<<(BB * HH + 255) / 256, 256>>>(Ubuf, hin, c0, bl, hout, cout);
    }
    float* hfin = bufs[LL & 1];          // == hbuf0 after 12 layers
    float* hrelu = bufs[(LL + 1) & 1];   // == hbuf1

    // 3) dense3 + relu (stay time-major)
    sgemm_kernel<<<gemm_grid(ROWS, HH), 256>>>(hfin, W3, b3, hrelu,
                                               ROWS, HH, HH, /*bias|relu*/ 3);

    // 4) dense4, remap back to batch-major rows (b*T+t)
    sgemm_kernel<<<gemm_grid(ROWS, OUTD), 256>>>(hrelu, W4, b4, out,
                                                 ROWS, OUTD, HH, /*bias|remap2*/ 1 | (2 << 2));
}

// round 2
// speedup vs baseline: 2.7321x; 2.7321x over previous
#include <cuda_runtime.h>
#include <cuda_bf16.h>
#include <math.h>
#include <stdint.h>

// Problem constants
#define BB 40      // batch
#define TT 20      // time
#define FEA 200
#define HH 1024
#define OUTD 1095
#define LL 12
#define ROWS (BB*TT)   // 800

// Scratch (device globals; no allocation allowed)
__device__ float g_h[2][ROWS * HH];     // ping-pong hidden activations, time-major [T,B,H]
__device__ float g_U[ROWS * 3 * HH];    // SRU pre-activations per layer
__device__ float g_cdump[BB * HH];      // sink for c_last if out buffer too small

// ---------------------------------------------------------------------------
// TF32 tensor-core GEMM: C[M,N] = A[M,K] * B[K,N] (+bias)(+relu)(+row remap)
// CTA tile 64x128, 128 threads (4 warps), warp tile 32x64, BK=16,
// mma.sync.aligned.m16n8k8.row.col.f32.tf32.tf32.f32, double-buffered smem.
// flags: bit0 bias, bit1 relu, bits[2:4] remap:
//   0: out_row = row
//   1: row is (b*T+t) -> out_row = t*B+b
//   2: row is (t*B+b) -> out_row = b*T+t
// ---------------------------------------------------------------------------
#define GBM 64
#define GBN 128
#define GBK 16
#define ASTRIDE 68   // 64 + 4 pad
#define BSTRIDE 132  // 128 + 4 pad

__device__ __forceinline__ uint32_t f2tf32(float x) {
    uint32_t r;
    asm("cvt.rna.tf32.f32 %0, %1;" : "=r"(r) : "f"(x));
    return r;
}

__global__ __launch_bounds__(128, 2)
void tf32gemm_kernel(const float* __restrict__ A, const float* __restrict__ B,
                     const float* __restrict__ bias, float* __restrict__ C,
                     int M, int N, int K, int flags)
{
    // smem tiles stored as tf32-rounded fp32 bit patterns
    __shared__ uint32_t As[2][GBK][ASTRIDE];   // [k][m]
    __shared__ uint32_t Bs[2][GBK][BSTRIDE];   // [k][n]

    const int tid  = threadIdx.x;
    const int lane = tid & 31;
    const int warp = tid >> 5;
    const int wm = warp >> 1;            // 0..1
    const int wn = warp & 1;             // 0..1
    const int q = lane & 3;              // 0..3
    const int g = lane >> 2;             // 0..7

    const int m0 = blockIdx.y * GBM;
    const int n0 = blockIdx.x * GBN;

    float acc[2][8][4];
#pragma unroll
    for (int mt = 0; mt < 2; mt++)
#pragma unroll
        for (int nt = 0; nt < 8; nt++)
#pragma unroll
            for (int e = 0; e < 4; e++) acc[mt][nt][e] = 0.0f;

    const int ntiles = (K + GBK - 1) / GBK;

    // ---- staging loads for one K-tile ----
    // A tile: 64 rows x 16 k -> 256 float4, 2 per thread
    // B tile: 16 k x 128 n   -> 4x (4 scalars) per thread
    float4 aStage[2];
    float  bStage[4][4];

    auto load_tile = [&](int kt) {
        const int kk = kt * GBK;
#pragma unroll
        for (int i = 0; i < 2; i++) {
            int idx  = tid + i * 128;       // 0..255
            int rowA = idx >> 2;            // 0..63
            int kc   = (idx & 3) * 4;       // 0,4,8,12
            int gm = m0 + rowA;
            int gk = kk + kc;
            if (gm < M && gk + 4 <= K) {
                aStage[i] = *reinterpret_cast<const float4*>(&A[(size_t)gm * K + gk]);
            } else {
                aStage[i] = make_float4(0.f, 0.f, 0.f, 0.f);
            }
        }
#pragma unroll
        for (int i = 0; i < 4; i++) {
            int idx  = tid + i * 128;       // 0..511
            int rowB = idx >> 5;            // 0..15
            int nc   = (idx & 31) * 4;      // 0..124
            int gk = kk + rowB;
            int gn = n0 + nc;
            const float* src = &B[(size_t)gk * N + gn];
            bool krow = (gk < K);
#pragma unroll
            for (int c = 0; c < 4; c++)
                bStage[i][c] = (krow && (gn + c) < N) ? src[c] : 0.0f;
        }
    };

    auto store_tile = [&](int buf) {
#pragma unroll
        for (int i = 0; i < 2; i++) {
            int idx  = tid + i * 128;
            int rowA = idx >> 2;
            int kc   = (idx & 3) * 4;
            As[buf][kc + 0][rowA] = f2tf32(aStage[i].x);
            As[buf][kc + 1][rowA] = f2tf32(aStage[i].y);
            As[buf][kc + 2][rowA] = f2tf32(aStage[i].z);
            As[buf][kc + 3][rowA] = f2tf32(aStage[i].w);
        }
#pragma unroll
        for (int i = 0; i < 4; i++) {
            int idx  = tid + i * 128;
            int rowB = idx >> 5;
            int nc   = (idx & 31) * 4;
#pragma unroll
            for (int c = 0; c < 4; c++)
                Bs[buf][rowB][nc + c] = f2tf32(bStage[i][c]);
        }
    };

    load_tile(0);
    store_tile(0);
    __syncthreads();

    for (int kt = 0; kt < ntiles; kt++) {
        int cur = kt & 1;
        if (kt + 1 < ntiles) load_tile(kt + 1);

        // compute: 2 k-steps of 8
#pragma unroll
        for (int s = 0; s < 2; s++) {
            const int kb = s * 8;
            uint32_t af[2][4];
#pragma unroll
            for (int mt = 0; mt < 2; mt++) {
                int mo = wm * 32 + mt * 16;
                af[mt][0] = As[cur][kb + q][mo + g];
                af[mt][1] = As[cur][kb + q][mo + g + 8];
                af[mt][2] = As[cur][kb + q + 4][mo + g];
                af[mt][3] = As[cur][kb + q + 4][mo + g + 8];
            }
            uint32_t bf[8][2];
#pragma unroll
            for (int nt = 0; nt < 8; nt++) {
                int no = wn * 64 + nt * 8;
                bf[nt][0] = Bs[cur][kb + q][no + g];
                bf[nt][1] = Bs[cur][kb + q + 4][no + g];
            }
#pragma unroll
            for (int mt = 0; mt < 2; mt++)
#pragma unroll
                for (int nt = 0; nt < 8; nt++) {
                    asm volatile(
                        "mma.sync.aligned.m16n8k8.row.col.f32.tf32.tf32.f32 "
                        "{%0,%1,%2,%3}, {%4,%5,%6,%7}, {%8,%9}, {%0,%1,%2,%3};\n"
                        : "+f"(acc[mt][nt][0]), "+f"(acc[mt][nt][1]),
                          "+f"(acc[mt][nt][2]), "+f"(acc[mt][nt][3])
                        : "r"(af[mt][0]), "r"(af[mt][1]), "r"(af[mt][2]), "r"(af[mt][3]),
                          "r"(bf[nt][0]), "r"(bf[nt][1]));
                }
        }

        if (kt + 1 < ntiles) store_tile((kt + 1) & 1);
        __syncthreads();
    }

    // ---- epilogue ----
    const bool has_bias = flags & 1;
    const bool do_relu  = flags & 2;
    const int remap     = (flags >> 2) & 3;

#pragma unroll
    for (int mt = 0; mt < 2; mt++) {
#pragma unroll
        for (int half = 0; half < 2; half++) {
            int row = m0 + wm * 32 + mt * 16 + g + half * 8;
            if (row >= M) continue;
            int out_row = row;
            if (remap == 1)      { int t = row % TT, b = row / TT; out_row = t * BB + b; }
            else if (remap == 2) { int t = row / BB, b = row % BB; out_row = b * TT + t; }
            float* crow = &C[(size_t)out_row * N];
#pragma unroll
            for (int nt = 0; nt < 8; nt++) {
#pragma unroll
                for (int cc = 0; cc < 2; cc++) {
                    int col = n0 + wn * 64 + nt * 8 + 2 * q + cc;
                    if (col >= N) continue;
                    float v = acc[mt][nt][half * 2 + cc];
                    if (has_bias) v += bias[col];
                    if (do_relu) v = fmaxf(v, 0.0f);
                    crow[col] = v;
                }
            }
        }
    }
}

// ---------------------------------------------------------------------------
// SRU recurrence + highway for one layer (time-major).
// ---------------------------------------------------------------------------
__global__ void sru_scan_kernel(const float* __restrict__ U,
                                const float* __restrict__ h_in,
                                const float* __restrict__ c0,
                                const float* __restrict__ b_lay,
                                float* __restrict__ h_out,
                                float* __restrict__ c_out)
{
    int idx = blockIdx.x * blockDim.x + threadIdx.x;   // [0, B*H)
    if (idx >= BB * HH) return;
    int b = idx / HH;
    int j = idx % HH;

    float c = c0[(size_t)b * HH + j];
    float bf = b_lay[j];
    float br = b_lay[HH + j];

#pragma unroll 4
    for (int t = 0; t < TT; t++) {
        int r = t * BB + b;
        size_t base = (size_t)r * (3 * HH);
        float xt = U[base + j];
        float uf = U[base + HH + j];
        float ur = U[base + 2 * HH + j];
        float f  = 1.0f / (1.0f + expf(-(uf + bf)));
        float rr = 1.0f / (1.0f + expf(-(ur + br)));
        c = f * c + (1.0f - f) * xt;
        float hprev = h_in[(size_t)r * HH + j];
        h_out[(size_t)r * HH + j] = rr * tanhf(c) + (1.0f - rr) * hprev;
    }
    c_out[(size_t)b * HH + j] = c;
}

// ---------------------------------------------------------------------------

static inline dim3 gemm_grid(int M, int N) {
    return dim3((N + GBN - 1) / GBN, (M + GBM - 1) / GBM);
}

extern "C" void kernel_launch(void* const* d_in, const int* in_sizes, int n_in,
                              void* d_out, int out_size)
{
    const float* x      = (const float*)d_in[0];   // [B,T,FEA]
    const float* hidden = (const float*)d_in[1];   // [L,B,H]
    const float* W1     = (const float*)d_in[2];   // [FEA,H]
    const float* b1     = (const float*)d_in[3];   // [H]
    const float* sruW   = (const float*)d_in[4];   // [L,H,3H]
    const float* srub   = (const float*)d_in[5];   // [L,2H]
    const float* W3     = (const float*)d_in[6];   // [H,H]
    const float* b3     = (const float*)d_in[7];   // [H]
    const float* W4     = (const float*)d_in[8];   // [H,OUT]
    const float* b4     = (const float*)d_in[9];   // [OUT]
    float* out = (float*)d_out;

    float* hbuf0; float* hbuf1; float* Ubuf; float* cdump;
    cudaGetSymbolAddress((void**)&hbuf0, g_h);
    hbuf1 = hbuf0 + (size_t)ROWS * HH;
    cudaGetSymbolAddress((void**)&Ubuf, g_U);
    cudaGetSymbolAddress((void**)&cdump, g_cdump);

    const int total_out = ROWS * OUTD + LL * BB * HH;
    const bool write_hidden = (out_size >= total_out);
    float* hid_out_base = write_hidden ? (out + (size_t)ROWS * OUTD) : nullptr;

    // 1) dense1: x[b*T+t, FEA] @ W1 -> h0 time-major [t*B+b, H]
    tf32gemm_kernel<<<gemm_grid(ROWS, HH), 128>>>(x, W1, b1, hbuf0,
                                                  ROWS, HH, FEA, 1 | (1 << 2));

    // 2) SRU layers
    float* bufs[2] = {hbuf0, hbuf1};
    for (int l = 0; l < LL; l++) {
        const float* hin  = bufs[l & 1];
        float*       hout = bufs[(l + 1) & 1];
        const float* Wl = sruW + (size_t)l * HH * 3 * HH;
        const float* bl = srub + (size_t)l * 2 * HH;
        const float* c0 = hidden + (size_t)l * BB * HH;
        float* cout = write_hidden ? (hid_out_base + (size_t)l * BB * HH) : cdump;

        tf32gemm_kernel<<<gemm_grid(ROWS, 3 * HH), 128>>>(hin, Wl, nullptr, Ubuf,
                                                          ROWS, 3 * HH, HH, 0);
        sru_scan_kernel<<<(BB * HH + 255) / 256, 256>>>(Ubuf, hin, c0, bl, hout, cout);
    }
    float* hfin  = bufs[LL & 1];
    float* hrelu = bufs[(LL + 1) & 1];

    // 3) dense3 + relu (stay time-major)
    tf32gemm_kernel<<<gemm_grid(ROWS, HH), 128>>>(hfin, W3, b3, hrelu,
                                                  ROWS, HH, HH, 3);

    // 4) dense4, remap back to batch-major rows (b*T+t)
    tf32gemm_kernel<<<gemm_grid(ROWS, OUTD), 128>>>(hrelu, W4, b4, out,
                                                    ROWS, OUTD, HH, 1 | (2 << 2));
}

// round 5
// speedup vs baseline: 3.4824x; 1.2746x over previous
#include <cuda_runtime.h>
#include <cuda_bf16.h>
#include <math.h>
#include <stdint.h>

// Problem constants
#define BB 40      // batch
#define TT 20      // time
#define FEA 200
#define HH 1024
#define OUTD 1095
#define LL 12
#define ROWS (BB*TT)   // 800

// Scratch (device globals; no allocation allowed)
__device__ float g_h[2][ROWS * HH];     // ping-pong hidden activations, time-major [T,B,H]
__device__ float g_U[ROWS * 3 * HH];    // SRU pre-activations per layer
__device__ float g_cdump[BB * HH];      // sink for c_last if out buffer too small

// ---------------------------------------------------------------------------
// TF32 tensor-core GEMM: C[M,N] = A[M,K] * B[K,N] (+bias)(+relu)(+row remap)
// CTA tile 64x128, 128 threads (4 warps 2x2), warp tile 32x64, BK=16,
// mma.sync.aligned.m16n8k8 tf32, double-buffered smem.
// smem holds k-pairs packed as float2 (k=q in .x, k=q+4 in .y) so fragment
// loads are conflict-free LDS.64 (plane stride 68/132 -> bank = 8q+2g).
// B global loads use float4 only when N % 4 == 0 (N=1095 rows are not
// 16B-aligned -> scalar fallback for dense4).
// flags: bit0 bias, bit1 relu, bits[2:4] remap:
//   0: out_row = row
//   1: row is (b*T+t) -> out_row = t*B+b
//   2: row is (t*B+b) -> out_row = b*T+t
// ---------------------------------------------------------------------------
#define GBM 64
#define GBN 128
#define GBK 16
#define APS 68    // A plane stride (m dim) in float2
#define BPS 132   // B plane stride (n dim) in float2

__device__ __forceinline__ float f2tf32f(float x) {
    uint32_t r;
    asm("cvt.rna.tf32.f32 %0, %1;" : "=r"(r) : "f"(x));
    return __uint_as_float(r);
}

__global__ __launch_bounds__(128, 2)
void tf32gemm_kernel(const float* __restrict__ A, const float* __restrict__ B,
                     const float* __restrict__ bias, float* __restrict__ C,
                     int M, int N, int K, int flags)
{
    // [db][s][q][m-or-n] of float2 (tf32-rounded fp32 bits)
    __shared__ float2 As[2][2][4][APS];
    __shared__ float2 Bs[2][2][4][BPS];

    const int tid  = threadIdx.x;
    const int lane = tid & 31;
    const int warp = tid >> 5;
    const int wm = warp >> 1;            // 0..1
    const int wn = warp & 1;             // 0..1
    const int q = lane & 3;              // 0..3
    const int g = lane >> 2;             // 0..7

    const int m0 = blockIdx.y * GBM;
    const int n0 = blockIdx.x * GBN;

    const bool nvec = ((N & 3) == 0);    // can we use float4 on B rows?

    float acc[2][8][4];
#pragma unroll
    for (int mt = 0; mt < 2; mt++)
#pragma unroll
        for (int nt = 0; nt < 8; nt++)
#pragma unroll
            for (int e = 0; e < 4; e++) acc[mt][nt][e] = 0.0f;

    const int ntiles = (K + GBK - 1) / GBK;

    // staging registers
    const int aRow = tid >> 1;           // 0..63
    const int aK   = (tid & 1) * 8;      // 0 or 8
    float4 aS[2];
    float  bS[4][4];

    float* Asf = reinterpret_cast<float*>(As);
    float* Bsf = reinterpret_cast<float*>(Bs);

    auto load_tile = [&](int kt) {
        const int kk = kt * GBK;
        const int gm = m0 + aRow;
#pragma unroll
        for (int i = 0; i < 2; i++) {
            int gk = kk + aK + i * 4;
            if (gm < M && gk + 4 <= K) {
                aS[i] = *reinterpret_cast<const float4*>(&A[(size_t)gm * K + gk]);
            } else if (gm < M && gk < K) {
                float t[4];
#pragma unroll
                for (int c = 0; c < 4; c++) t[c] = (gk + c < K) ? A[(size_t)gm * K + gk + c] : 0.0f;
                aS[i] = make_float4(t[0], t[1], t[2], t[3]);
            } else {
                aS[i] = make_float4(0.f, 0.f, 0.f, 0.f);
            }
        }
#pragma unroll
        for (int i = 0; i < 4; i++) {
            int idx  = tid + i * 128;       // 0..511
            int rowB = idx >> 5;            // 0..15
            int n    = (idx & 31) * 4;      // 0..124
            int gk = kk + rowB;
            int gn = n0 + n;
            if (nvec && gk < K && gn + 4 <= N) {
                float4 v = *reinterpret_cast<const float4*>(&B[(size_t)gk * N + gn]);
                bS[i][0] = v.x; bS[i][1] = v.y; bS[i][2] = v.z; bS[i][3] = v.w;
            } else if (gk < K) {
                const float* src = &B[(size_t)gk * N];
#pragma unroll
                for (int c = 0; c < 4; c++)
                    bS[i][c] = (gn + c < N) ? src[gn + c] : 0.0f;
            } else {
#pragma unroll
                for (int c = 0; c < 4; c++) bS[i][c] = 0.0f;
            }
        }
    };

    auto store_tile = [&](int buf) {
        // A: element (k = aK + i*4 + c, m = aRow)
#pragma unroll
        for (int i = 0; i < 2; i++) {
            const float v[4] = {aS[i].x, aS[i].y, aS[i].z, aS[i].w};
#pragma unroll
            for (int c = 0; c < 4; c++) {
                int k = aK + i * 4 + c;
                int s = k >> 3, o = k & 7;
                int qq = o & 3, hf = o >> 2;
                Asf[(((buf * 2 + s) * 4 + qq) * APS + aRow) * 2 + hf] = f2tf32f(v[c]);
            }
        }
        // B: element (k = rowB, n = n + c)
#pragma unroll
        for (int i = 0; i < 4; i++) {
            int idx  = tid + i * 128;
            int rowB = idx >> 5;
            int n    = (idx & 31) * 4;
            int s = rowB >> 3, o = rowB & 7;
            int qq = o & 3, hf = o >> 2;
            float* base = &Bsf[(((buf * 2 + s) * 4 + qq) * BPS) * 2 + hf];
#pragma unroll
            for (int c = 0; c < 4; c++)
                base[(n + c) * 2] = f2tf32f(bS[i][c]);
        }
    };

    load_tile(0);
    store_tile(0);
    __syncthreads();

    for (int kt = 0; kt < ntiles; kt++) {
        int cur = kt & 1;
        if (kt + 1 < ntiles) load_tile(kt + 1);

#pragma unroll
        for (int s = 0; s < 2; s++) {
            // A fragments: 4x LDS.64
            uint32_t af[2][4];
#pragma unroll
            for (int mt = 0; mt < 2; mt++) {
                int mo = wm * 32 + mt * 16;
                float2 f0 = As[cur][s][q][mo + g];
                float2 f1 = As[cur][s][q][mo + g + 8];
                af[mt][0] = __float_as_uint(f0.x);
                af[mt][1] = __float_as_uint(f1.x);
                af[mt][2] = __float_as_uint(f0.y);
                af[mt][3] = __float_as_uint(f1.y);
            }
            // B fragments: 8x LDS.64
            uint32_t bf[8][2];
#pragma unroll
            for (int nt = 0; nt < 8; nt++) {
                float2 f = Bs[cur][s][q][wn * 64 + nt * 8 + g];
                bf[nt][0] = __float_as_uint(f.x);
                bf[nt][1] = __float_as_uint(f.y);
            }
#pragma unroll
            for (int mt = 0; mt < 2; mt++)
#pragma unroll
                for (int nt = 0; nt < 8; nt++) {
                    asm volatile(
                        "mma.sync.aligned.m16n8k8.row.col.f32.tf32.tf32.f32 "
                        "{%0,%1,%2,%3}, {%4,%5,%6,%7}, {%8,%9}, {%0,%1,%2,%3};\n"
                        : "+f"(acc[mt][nt][0]), "+f"(acc[mt][nt][1]),
                          "+f"(acc[mt][nt][2]), "+f"(acc[mt][nt][3])
                        : "r"(af[mt][0]), "r"(af[mt][1]), "r"(af[mt][2]), "r"(af[mt][3]),
                          "r"(bf[nt][0]), "r"(bf[nt][1]));
                }
        }

        if (kt + 1 < ntiles) store_tile((kt + 1) & 1);
        __syncthreads();
    }

    // ---- epilogue ----
    const bool has_bias = flags & 1;
    const bool do_relu  = flags & 2;
    const int remap     = (flags >> 2) & 3;

#pragma unroll
    for (int mt = 0; mt < 2; mt++) {
#pragma unroll
        for (int half = 0; half < 2; half++) {
            int row = m0 + wm * 32 + mt * 16 + g + half * 8;
            if (row >= M) continue;
            int out_row = row;
            if (remap == 1)      { int t = row % TT, b = row / TT; out_row = t * BB + b; }
            else if (remap == 2) { int t = row / BB, b = row % BB; out_row = b * TT + t; }
            float* crow = &C[(size_t)out_row * N];
#pragma unroll
            for (int nt = 0; nt < 8; nt++) {
#pragma unroll
                for (int cc = 0; cc < 2; cc++) {
                    int col = n0 + wn * 64 + nt * 8 + 2 * q + cc;
                    if (col >= N) continue;
                    float v = acc[mt][nt][half * 2 + cc];
                    if (has_bias) v += bias[col];
                    if (do_relu) v = fmaxf(v, 0.0f);
                    crow[col] = v;
                }
            }
        }
    }
}

// ---------------------------------------------------------------------------
// SRU recurrence + highway for one layer (time-major), software-pipelined.
// ---------------------------------------------------------------------------
__global__ void sru_scan_kernel(const float* __restrict__ U,
                                const float* __restrict__ h_in,
                                const float* __restrict__ c0,
                                const float* __restrict__ b_lay,
                                float* __restrict__ h_out,
                                float* __restrict__ c_out)
{
    int idx = blockIdx.x * blockDim.x + threadIdx.x;   // [0, B*H)
    if (idx >= BB * HH) return;
    int b = idx / HH;
    int j = idx % HH;

    float c = c0[(size_t)b * HH + j];
    const float bf = b_lay[j];
    const float br = b_lay[HH + j];

    // prefetch t=0
    size_t base = (size_t)b * (3 * HH);
    float xt = U[base + j];
    float uf = U[base + HH + j];
    float ur = U[base + 2 * HH + j];
    float hp = h_in[(size_t)b * HH + j];

#pragma unroll
    for (int t = 0; t < TT; t++) {
        float nxt = 0.f, nuf = 0.f, nur = 0.f, nhp = 0.f;
        if (t + 1 < TT) {
            int r = (t + 1) * BB + b;
            size_t nb = (size_t)r * (3 * HH);
            nxt = U[nb + j];
            nuf = U[nb + HH + j];
            nur = U[nb + 2 * HH + j];
            nhp = h_in[(size_t)r * HH + j];
        }
        float f  = 1.0f / (1.0f + __expf(-(uf + bf)));
        float rr = 1.0f / (1.0f + __expf(-(ur + br)));
        c = f * c + (1.0f - f) * xt;
        int r = t * BB + b;
        h_out[(size_t)r * HH + j] = rr * tanhf(c) + (1.0f - rr) * hp;
        xt = nxt; uf = nuf; ur = nur; hp = nhp;
    }
    c_out[(size_t)b * HH + j] = c;
}

// ---------------------------------------------------------------------------

static inline dim3 gemm_grid(int M, int N) {
    return dim3((N + GBN - 1) / GBN, (M + GBM - 1) / GBM);
}

extern "C" void kernel_launch(void* const* d_in, const int* in_sizes, int n_in,
                              void* d_out, int out_size)
{
    const float* x      = (const float*)d_in[0];   // [B,T,FEA]
    const float* hidden = (const float*)d_in[1];   // [L,B,H]
    const float* W1     = (const float*)d_in[2];   // [FEA,H]
    const float* b1     = (const float*)d_in[3];   // [H]
    const float* sruW   = (const float*)d_in[4];   // [L,H,3H]
    const float* srub   = (const float*)d_in[5];   // [L,2H]
    const float* W3     = (const float*)d_in[6];   // [H,H]
    const float* b3     = (const float*)d_in[7];   // [H]
    const float* W4     = (const float*)d_in[8];   // [H,OUT]
    const float* b4     = (const float*)d_in[9];   // [OUT]
    float* out = (float*)d_out;

    float* hbuf0; float* hbuf1; float* Ubuf; float* cdump;
    cudaGetSymbolAddress((void**)&hbuf0, g_h);
    hbuf1 = hbuf0 + (size_t)ROWS * HH;
    cudaGetSymbolAddress((void**)&Ubuf, g_U);
    cudaGetSymbolAddress((void**)&cdump, g_cdump);

    const int total_out = ROWS * OUTD + LL * BB * HH;
    const bool write_hidden = (out_size >= total_out);
    float* hid_out_base = write_hidden ? (out + (size_t)ROWS * OUTD) : nullptr;

    // 1) dense1: x[b*T+t, FEA] @ W1 -> h0 time-major [t*B+b, H]
    tf32gemm_kernel<<<gemm_grid(ROWS, HH), 128>>>(x, W1, b1, hbuf0,
                                                  ROWS, HH, FEA, 1 | (1 << 2));

    // 2) SRU layers
    float* bufs[2] = {hbuf0, hbuf1};
    for (int l = 0; l < LL; l++) {
        const float* hin  = bufs[l & 1];
        float*       hout = bufs[(l + 1) & 1];
        const float* Wl = sruW + (size_t)l * HH * 3 * HH;
        const float* bl = srub + (size_t)l * 2 * HH;
        const float* c0 = hidden + (size_t)l * BB * HH;
        float* cout = write_hidden ? (hid_out_base + (size_t)l * BB * HH) : cdump;

        tf32gemm_kernel<<<gemm_grid(ROWS, 3 * HH), 128>>>(hin, Wl, nullptr, Ubuf,
                                                          ROWS, 3 * HH, HH, 0);
        sru_scan_kernel<<<(BB * HH + 255) / 256, 256>>>(Ubuf, hin, c0, bl, hout, cout);
    }
    float* hfin  = bufs[LL & 1];
    float* hrelu = bufs[(LL + 1) & 1];

    // 3) dense3 + relu (stay time-major)
    tf32gemm_kernel<<<gemm_grid(ROWS, HH), 128>>>(hfin, W3, b3, hrelu,
                                                  ROWS, HH, HH, 3);

    // 4) dense4, remap back to batch-major rows (b*T+t)
    tf32gemm_kernel<<<gemm_grid(ROWS, OUTD), 128>>>(hrelu, W4, b4, out,
                                                    ROWS, OUTD, HH, 1 | (2 << 2));
}

// round 11
// speedup vs baseline: 3.6862x; 1.0585x over previous
#include <cuda_runtime.h>
#include <cuda_bf16.h>
#include <math.h>
#include <stdint.h>

// Problem constants
#define BB 40
#define TT 20
#define FEA 200
#define HH 1024
#define OUTD 1095
#define LL 12
#define ROWS (BB*TT)   // 800

// Scratch (device globals; no allocation allowed)
__device__ float g_h[2][ROWS * HH];        // ping-pong activations, time-major
__device__ float g_U[2][ROWS * 3 * HH];    // split-K partial buffers
__device__ float g_cdump[BB * HH];

// ---------------------------------------------------------------------------
// TF32 tensor-core GEMM (mma.sync m16n8k8), CTA 64x128, BK=16, 4 warps 2x2,
// warp tile 32x64, double-buffered smem with packed (k=q, k=q+4) float2 pairs.
// B-tile stores are STS.128 (2-row packing) to kill the 8-way STS conflicts.
// Split-K via gridDim.z: chunk = koff_per_z, partial z writes to C + z*partStride.
// flags: bit0 bias, bit1 relu, bits[2:4] remap (1: bT->tB, 2: tB->bT)
// ---------------------------------------------------------------------------
#define GBM 64
#define GBN 128
#define GBK 16
#define APS 68    // A plane stride (float2 units)
#define BPS 132   // B plane stride (float2 units)

__device__ __forceinline__ float f2tf32f(float x) {
    uint32_t r;
    asm("cvt.rna.tf32.f32 %0, %1;" : "=r"(r) : "f"(x));
    return __uint_as_float(r);
}

__global__ __launch_bounds__(128, 3)
void tf32gemm_kernel(const float* __restrict__ A, const float* __restrict__ B,
                     const float* __restrict__ bias, float* __restrict__ C,
                     int M, int N, int K, int koff_per_z, int partStride, int flags)
{
    __shared__ float2 As[2][2][4][APS];
    __shared__ float2 Bs[2][2][4][BPS];

    const int tid  = threadIdx.x;
    const int lane = tid & 31;
    const int warp = tid >> 5;
    const int wm = warp >> 1;
    const int wn = warp & 1;
    const int q = lane & 3;
    const int g = lane >> 2;

    const int m0 = blockIdx.y * GBM;
    const int n0 = blockIdx.x * GBN;

    const int k0 = blockIdx.z * koff_per_z;
    const int k1 = (k0 + koff_per_z < K) ? (k0 + koff_per_z) : K;
    float* Cz = C + (size_t)blockIdx.z * partStride;

    const bool nvec = ((N & 3) == 0);

    float acc[2][8][4];
#pragma unroll
    for (int mt = 0; mt < 2; mt++)
#pragma unroll
        for (int nt = 0; nt < 8; nt++)
#pragma unroll
            for (int e = 0; e < 4; e++) acc[mt][nt][e] = 0.0f;

    const int ntiles = (k1 - k0 + GBK - 1) / GBK;

    // A staging: thread -> (row = tid>>1, k-half = (tid&1)*8), 2 x float4
    const int aRow = tid >> 1;
    const int aK   = (tid & 1) * 8;
    float4 aS[2];
    // B staging: 2 units; unit = tid + u*128 -> plane p = unit>>5 (s=p>>2,q=p&3),
    // nq = unit&31; loads rows k=8s+q and k=8s+q+4 at n=4*nq (4 cols each).
    float bS[2][2][4];   // [unit][row(k/k+4)][col]

    float* Asf = reinterpret_cast<float*>(As);

    auto load_tile = [&](int kt) {
        const int kk = k0 + kt * GBK;
        const int gm = m0 + aRow;
#pragma unroll
        for (int i = 0; i < 2; i++) {
            int gk = kk + aK + i * 4;
            if (gm < M && gk + 4 <= k1) {
                aS[i] = *reinterpret_cast<const float4*>(&A[(size_t)gm * K + gk]);
            } else if (gm < M && gk < k1) {
                float t[4];
#pragma unroll
                for (int c = 0; c < 4; c++) t[c] = (gk + c < k1) ? A[(size_t)gm * K + gk + c] : 0.f;
                aS[i] = make_float4(t[0], t[1], t[2], t[3]);
            } else {
                aS[i] = make_float4(0.f, 0.f, 0.f, 0.f);
            }
        }
#pragma unroll
        for (int u = 0; u < 2; u++) {
            int unit = tid + u * 128;
            int p  = unit >> 5;
            int nq = unit & 31;
            int ss = p >> 2, qq = p & 3;
            int gn = n0 + nq * 4;
#pragma unroll
            for (int rr = 0; rr < 2; rr++) {
                int gk = kk + ss * 8 + qq + rr * 4;
                if (gk < k1) {
                    if (nvec && gn + 4 <= N) {
                        float4 v = *reinterpret_cast<const float4*>(&B[(size_t)gk * N + gn]);
                        bS[u][rr][0] = v.x; bS[u][rr][1] = v.y; bS[u][rr][2] = v.z; bS[u][rr][3] = v.w;
                    } else {
                        const float* src = &B[(size_t)gk * N];
#pragma unroll
                        for (int c = 0; c < 4; c++)
                            bS[u][rr][c] = (gn + c < N) ? src[gn + c] : 0.f;
                    }
                } else {
#pragma unroll
                    for (int c = 0; c < 4; c++) bS[u][rr][c] = 0.f;
                }
            }
        }
    };

    auto store_tile = [&](int buf) {
        // A: scalar STS (2-way conflicts, cheap)
#pragma unroll
        for (int i = 0; i < 2; i++) {
            const float v[4] = {aS[i].x, aS[i].y, aS[i].z, aS[i].w};
#pragma unroll
            for (int c = 0; c < 4; c++) {
                int k = aK + i * 4 + c;
                int s = k >> 3, o = k & 7;
                int qq = o & 3, hf = o >> 2;
                Asf[(((buf * 2 + s) * 4 + qq) * APS + aRow) * 2 + hf] = f2tf32f(v[c]);
            }
        }
        // B: 2x STS.128 per unit, packed (kq, kq+4) pairs for 4 consecutive n
#pragma unroll
        for (int u = 0; u < 2; u++) {
            int unit = tid + u * 128;
            int p  = unit >> 5;
            int nq = unit & 31;
            int ss = p >> 2, qq = p & 3;
            float4 s0 = make_float4(f2tf32f(bS[u][0][0]), f2tf32f(bS[u][1][0]),
                                    f2tf32f(bS[u][0][1]), f2tf32f(bS[u][1][1]));
            float4 s1 = make_float4(f2tf32f(bS[u][0][2]), f2tf32f(bS[u][1][2]),
                                    f2tf32f(bS[u][0][3]), f2tf32f(bS[u][1][3]));
            float4* base = reinterpret_cast<float4*>(&Bs[buf][ss][qq][nq * 4]);
            base[0] = s0;
            base[1] = s1;
        }
    };

    load_tile(0);
    store_tile(0);
    __syncthreads();

    for (int kt = 0; kt < ntiles; kt++) {
        int cur = kt & 1;
        if (kt + 1 < ntiles) load_tile(kt + 1);

#pragma unroll
        for (int s = 0; s < 2; s++) {
            uint32_t af[2][4];
#pragma unroll
            for (int mt = 0; mt < 2; mt++) {
                int mo = wm * 32 + mt * 16;
                float2 f0 = As[cur][s][q][mo + g];
                float2 f1 = As[cur][s][q][mo + g + 8];
                af[mt][0] = __float_as_uint(f0.x);
                af[mt][1] = __float_as_uint(f1.x);
                af[mt][2] = __float_as_uint(f0.y);
                af[mt][3] = __float_as_uint(f1.y);
            }
            uint32_t bf[8][2];
#pragma unroll
            for (int nt = 0; nt < 8; nt++) {
                float2 f = Bs[cur][s][q][wn * 64 + nt * 8 + g];
                bf[nt][0] = __float_as_uint(f.x);
                bf[nt][1] = __float_as_uint(f.y);
            }
#pragma unroll
            for (int mt = 0; mt < 2; mt++)
#pragma unroll
                for (int nt = 0; nt < 8; nt++) {
                    asm volatile(
                        "mma.sync.aligned.m16n8k8.row.col.f32.tf32.tf32.f32 "
                        "{%0,%1,%2,%3}, {%4,%5,%6,%7}, {%8,%9}, {%0,%1,%2,%3};\n"
                        : "+f"(acc[mt][nt][0]), "+f"(acc[mt][nt][1]),
                          "+f"(acc[mt][nt][2]), "+f"(acc[mt][nt][3])
                        : "r"(af[mt][0]), "r"(af[mt][1]), "r"(af[mt][2]), "r"(af[mt][3]),
                          "r"(bf[nt][0]), "r"(bf[nt][1]));
                }
        }

        if (kt + 1 < ntiles) store_tile((kt + 1) & 1);
        __syncthreads();
    }

    // ---- epilogue ----
    const bool has_bias = flags & 1;
    const bool do_relu  = flags & 2;
    const int remap     = (flags >> 2) & 3;

#pragma unroll
    for (int mt = 0; mt < 2; mt++) {
#pragma unroll
        for (int half = 0; half < 2; half++) {
            int row = m0 + wm * 32 + mt * 16 + g + half * 8;
            if (row >= M) continue;
            int out_row = row;
            if (remap == 1)      { int t = row % TT, b = row / TT; out_row = t * BB + b; }
            else if (remap == 2) { int t = row / BB, b = row % BB; out_row = b * TT + t; }
            float* crow = &Cz[(size_t)out_row * N];
#pragma unroll
            for (int nt = 0; nt < 8; nt++) {
#pragma unroll
                for (int cc = 0; cc < 2; cc++) {
                    int col = n0 + wn * 64 + nt * 8 + 2 * q + cc;
                    if (col >= N) continue;
                    float v = acc[mt][nt][half * 2 + cc];
                    if (has_bias) v += bias[col];
                    if (do_relu) v = fmaxf(v, 0.0f);
                    crow[col] = v;
                }
            }
        }
    }
}

// ---------------------------------------------------------------------------
// SRU scan: sums the two split-K partials of U, then recurrence + highway.
// ---------------------------------------------------------------------------
__global__ void sru_scan_kernel(const float* __restrict__ U0,
                                const float* __restrict__ U1,
                                const float* __restrict__ h_in,
                                const float* __restrict__ c0,
                                const float* __restrict__ b_lay,
                                float* __restrict__ h_out,
                                float* __restrict__ c_out)
{
    int idx = blockIdx.x * blockDim.x + threadIdx.x;
    if (idx >= BB * HH) return;
    int b = idx / HH;
    int j = idx % HH;

    float c = c0[(size_t)b * HH + j];
    const float bf = b_lay[j];
    const float br = b_lay[HH + j];

    size_t base = (size_t)b * (3 * HH);
    float xt = U0[base + j]          + U1[base + j];
    float uf = U0[base + HH + j]     + U1[base + HH + j];
    float ur = U0[base + 2 * HH + j] + U1[base + 2 * HH + j];
    float hp = h_in[(size_t)b * HH + j];

#pragma unroll
    for (int t = 0; t < TT; t++) {
        float nxt = 0.f, nuf = 0.f, nur = 0.f, nhp = 0.f;
        if (t + 1 < TT) {
            int r = (t + 1) * BB + b;
            size_t nb = (size_t)r * (3 * HH);
            nxt = U0[nb + j]          + U1[nb + j];
            nuf = U0[nb + HH + j]     + U1[nb + HH + j];
            nur = U0[nb + 2 * HH + j] + U1[nb + 2 * HH + j];
            nhp = h_in[(size_t)r * HH + j];
        }
        float f  = 1.0f / (1.0f + __expf(-(uf + bf)));
        float rr = 1.0f / (1.0f + __expf(-(ur + br)));
        c = f * c + (1.0f - f) * xt;
        int r = t * BB + b;
        h_out[(size_t)r * HH + j] = rr * tanhf(c) + (1.0f - rr) * hp;
        xt = nxt; uf = nuf; ur = nur; hp = nhp;
    }
    c_out[(size_t)b * HH + j] = c;
}

// ---------------------------------------------------------------------------
// Combine split-K partials for dense3/dense4: C = act(p0+p1+bias), opt remap.
// rows are time-major (t*BB+b); remap2 converts to batch-major (b*TT+t).
// ---------------------------------------------------------------------------
__global__ void combine_kernel(const float* __restrict__ p0,
                               const float* __restrict__ p1,
                               const float* __restrict__ bias,
                               float* __restrict__ C, int N, int flags)
{
    int idx = blockIdx.x * blockDim.x + threadIdx.x;
    if (idx >= ROWS * N) return;
    int row = idx / N;
    int col = idx - row * N;
    float v = p0[idx] + p1[idx];
    if (flags & 1) v += bias[col];
    if (flags & 2) v = fmaxf(v, 0.0f);
    int orow = row;
    if (((flags >> 2) & 3) == 2) { int t = row / BB, b = row % BB; orow = b * TT + t; }
    C[(size_t)orow * N + col] = v;
}

// ---------------------------------------------------------------------------

extern "C" void kernel_launch(void* const* d_in, const int* in_sizes, int n_in,
                              void* d_out, int out_size)
{
    const float* x      = (const float*)d_in[0];
    const float* hidden = (const float*)d_in[1];
    const float* W1     = (const float*)d_in[2];
    const float* b1     = (const float*)d_in[3];
    const float* sruW   = (const float*)d_in[4];
    const float* srub   = (const float*)d_in[5];
    const float* W3     = (const float*)d_in[6];
    const float* b3     = (const float*)d_in[7];
    const float* W4     = (const float*)d_in[8];
    const float* b4     = (const float*)d_in[9];
    float* out = (float*)d_out;

    float* hbuf0; float* hbuf1; float* Ubuf; float* cdump;
    cudaGetSymbolAddress((void**)&hbuf0, g_h);
    hbuf1 = hbuf0 + (size_t)ROWS * HH;
    cudaGetSymbolAddress((void**)&Ubuf, g_U);
    cudaGetSymbolAddress((void**)&cdump, g_cdump);
    const int SLAB = ROWS * 3 * HH;
    float* Ubuf1 = Ubuf + SLAB;

    const int total_out = ROWS * OUTD + LL * BB * HH;
    const bool write_hidden = (out_size >= total_out);
    float* hid_out_base = write_hidden ? (out + (size_t)ROWS * OUTD) : nullptr;

    // 1) dense1: x @ W1 -> time-major (unsplit, K=200)
    tf32gemm_kernel<<<dim3(HH / GBN, (ROWS + GBM - 1) / GBM, 1), 128>>>(
        x, W1, b1, hbuf0, ROWS, HH, FEA, FEA, 0, 1 | (1 << 2));

    // 2) SRU layers: split-K=2 GEMM into partial slabs, scan fuses the sum
    float* bufs[2] = {hbuf0, hbuf1};
    for (int l = 0; l < LL; l++) {
        const float* hin  = bufs[l & 1];
        float*       hout = bufs[(l + 1) & 1];
        const float* Wl = sruW + (size_t)l * HH * 3 * HH;
        const float* bl = srub + (size_t)l * 2 * HH;
        const float* c0 = hidden + (size_t)l * BB * HH;
        float* cout = write_hidden ? (hid_out_base + (size_t)l * BB * HH) : cdump;

        tf32gemm_kernel<<<dim3(3 * HH / GBN, (ROWS + GBM - 1) / GBM, 2), 128>>>(
            hin, Wl, nullptr, Ubuf, ROWS, 3 * HH, HH, HH / 2, SLAB, 0);
        sru_scan_kernel<<<(BB * HH + 255) / 256, 256>>>(Ubuf, Ubuf1, hin, c0, bl, hout, cout);
    }
    float* hfin  = bufs[LL & 1];
    float* hrelu = bufs[(LL + 1) & 1];

    // 3) dense3 (split-K=2) + combine(bias, relu)
    tf32gemm_kernel<<<dim3(HH / GBN, (ROWS + GBM - 1) / GBM, 2), 128>>>(
        hfin, W3, nullptr, Ubuf, ROWS, HH, HH, HH / 2, SLAB, 0);
    combine_kernel<<<(ROWS * HH + 255) / 256, 256>>>(Ubuf, Ubuf1, b3, hrelu, HH, 3);

    // 4) dense4 (split-K=2) + combine(bias, remap to batch-major)
    tf32gemm_kernel<<<dim3((OUTD + GBN - 1) / GBN, (ROWS + GBM - 1) / GBM, 2), 128>>>(
        hrelu, W4, nullptr, Ubuf, ROWS, OUTD, HH, HH / 2, SLAB, 0);
    combine_kernel<<<(ROWS * OUTD + 255) / 256, 256>>>(Ubuf, Ubuf1, b4, out, OUTD, 1 | (2 << 2));
}

// round 12
// speedup vs baseline: 3.9181x; 1.0629x over previous
#include <cuda_runtime.h>
#include <cuda_bf16.h>
#include <math.h>
#include <stdint.h>

// Problem constants
#define BB 40
#define TT 20
#define FEA 200
#define HH 1024
#define OUTD 1095
#define LL 12
#define ROWS (BB*TT)   // 800
#define W4LD 1096      // padded row stride for W4 tf32 copy

// Scratch (device globals; no allocation allowed)
__device__ float g_h[2][ROWS * HH];        // exact activations (highway path)
__device__ float g_ht[2][ROWS * HH];       // tf32-rounded twins (GEMM A operands)
__device__ float g_U[2][ROWS * 3 * HH];    // split-K partial buffers
__device__ float g_hrelu_t[ROWS * HH];     // rounded dense3 output (dense4 A)
__device__ float g_cdump[BB * HH];
// tf32-rounded static operands
__device__ float g_xt[ROWS * FEA];
__device__ float g_w1t[FEA * HH];
__device__ float g_wst[LL * HH * 3 * HH];
__device__ float g_w3t[HH * HH];
__device__ float g_w4t[HH * W4LD + 256];   // padded + slack for tile overreach

__device__ __forceinline__ float f2tf32f(float x) {
    uint32_t r;
    asm("cvt.rna.tf32.f32 %0, %1;" : "=r"(r) : "f"(x));
    return __uint_as_float(r);
}

// ---------------------------------------------------------------------------
// One-time conversions (per launch): round to tf32 bit patterns.
// ---------------------------------------------------------------------------
__global__ void round_copy4(const float4* __restrict__ src, float4* __restrict__ dst, int n4)
{
    int i = blockIdx.x * blockDim.x + threadIdx.x;
    if (i >= n4) return;
    float4 v = src[i];
    dst[i] = make_float4(f2tf32f(v.x), f2tf32f(v.y), f2tf32f(v.z), f2tf32f(v.w));
}
__global__ void round_pad_w4(const float* __restrict__ src, float* __restrict__ dst)
{
    int i = blockIdx.x * blockDim.x + threadIdx.x;   // over HH*W4LD
    if (i >= HH * W4LD) return;
    int k = i / W4LD, n = i - k * W4LD;
    dst[i] = (n < OUTD) ? f2tf32f(src[(size_t)k * OUTD + n]) : 0.0f;
}

// ---------------------------------------------------------------------------
// TF32 tensor-core GEMM (mma.sync m16n8k8), CTA 64x128, BK=16, 4 warps 2x2.
// Operands are PRE-ROUNDED to tf32 — no cvt in the hot loop.
// ldb = B row stride. Optional C2: tf32-rounded copy of the output.
// flags: bit0 bias, bit1 relu, bits[2:4] remap (1: bT->tB, 2: tB->bT)
// ---------------------------------------------------------------------------
#define GBM 64
#define GBN 128
#define GBK 16
#define APS 68
#define BPS 132

__global__ __launch_bounds__(128, 3)
void tf32gemm_kernel(const float* __restrict__ A, const float* __restrict__ B,
                     const float* __restrict__ bias, float* __restrict__ C,
                     float* __restrict__ C2,
                     int M, int N, int K, int ldb, int koff_per_z, int partStride, int flags)
{
    __shared__ float2 As[2][2][4][APS];
    __shared__ float2 Bs[2][2][4][BPS];

    const int tid  = threadIdx.x;
    const int lane = tid & 31;
    const int warp = tid >> 5;
    const int wm = warp >> 1;
    const int wn = warp & 1;
    const int q = lane & 3;
    const int g = lane >> 2;

    const int m0 = blockIdx.y * GBM;
    const int n0 = blockIdx.x * GBN;

    const int k0 = blockIdx.z * koff_per_z;
    const int k1 = (k0 + koff_per_z < K) ? (k0 + koff_per_z) : K;
    float* Cz = C + (size_t)blockIdx.z * partStride;

    float acc[2][8][4];
#pragma unroll
    for (int mt = 0; mt < 2; mt++)
#pragma unroll
        for (int nt = 0; nt < 8; nt++)
#pragma unroll
            for (int e = 0; e < 4; e++) acc[mt][nt][e] = 0.0f;

    const int ntiles = (k1 - k0 + GBK - 1) / GBK;

    const int aRow = tid >> 1;
    const int aK   = (tid & 1) * 8;
    float4 aS[2];
    float bS[2][2][4];

    float* Asf = reinterpret_cast<float*>(As);

    auto load_tile = [&](int kt) {
        const int kk = k0 + kt * GBK;
        const int gm = m0 + aRow;
#pragma unroll
        for (int i = 0; i < 2; i++) {
            int gk = kk + aK + i * 4;
            if (gm < M && gk + 4 <= k1) {
                aS[i] = *reinterpret_cast<const float4*>(&A[(size_t)gm * K + gk]);
            } else if (gm < M && gk < k1) {
                float t[4];
#pragma unroll
                for (int c = 0; c < 4; c++) t[c] = (gk + c < k1) ? A[(size_t)gm * K + gk + c] : 0.f;
                aS[i] = make_float4(t[0], t[1], t[2], t[3]);
            } else {
                aS[i] = make_float4(0.f, 0.f, 0.f, 0.f);
            }
        }
#pragma unroll
        for (int u = 0; u < 2; u++) {
            int unit = tid + u * 128;
            int p  = unit >> 5;
            int nq = unit & 31;
            int ss = p >> 2, qq = p & 3;
            int gn = n0 + nq * 4;
#pragma unroll
            for (int rr = 0; rr < 2; rr++) {
                int gk = kk + ss * 8 + qq + rr * 4;
                if (gk < k1) {
                    float4 v = *reinterpret_cast<const float4*>(&B[(size_t)gk * ldb + gn]);
                    bS[u][rr][0] = v.x; bS[u][rr][1] = v.y; bS[u][rr][2] = v.z; bS[u][rr][3] = v.w;
                } else {
#pragma unroll
                    for (int c = 0; c < 4; c++) bS[u][rr][c] = 0.f;
                }
            }
        }
    };

    auto store_tile = [&](int buf) {
#pragma unroll
        for (int i = 0; i < 2; i++) {
            const float v[4] = {aS[i].x, aS[i].y, aS[i].z, aS[i].w};
#pragma unroll
            for (int c = 0; c < 4; c++) {
                int k = aK + i * 4 + c;
                int s = k >> 3, o = k & 7;
                int qq = o & 3, hf = o >> 2;
                Asf[(((buf * 2 + s) * 4 + qq) * APS + aRow) * 2 + hf] = v[c];
            }
        }
#pragma unroll
        for (int u = 0; u < 2; u++) {
            int unit = tid + u * 128;
            int p  = unit >> 5;
            int nq = unit & 31;
            int ss = p >> 2, qq = p & 3;
            float4 s0 = make_float4(bS[u][0][0], bS[u][1][0], bS[u][0][1], bS[u][1][1]);
            float4 s1 = make_float4(bS[u][0][2], bS[u][1][2], bS[u][0][3], bS[u][1][3]);
            float4* base = reinterpret_cast<float4*>(&Bs[buf][ss][qq][nq * 4]);
            base[0] = s0;
            base[1] = s1;
        }
    };

    load_tile(0);
    store_tile(0);
    __syncthreads();

    for (int kt = 0; kt < ntiles; kt++) {
        int cur = kt & 1;
        if (kt + 1 < ntiles) load_tile(kt + 1);

#pragma unroll
        for (int s = 0; s < 2; s++) {
            uint32_t af[2][4];
#pragma unroll
            for (int mt = 0; mt < 2; mt++) {
                int mo = wm * 32 + mt * 16;
                float2 f0 = As[cur][s][q][mo + g];
                float2 f1 = As[cur][s][q][mo + g + 8];
                af[mt][0] = __float_as_uint(f0.x);
                af[mt][1] = __float_as_uint(f1.x);
                af[mt][2] = __float_as_uint(f0.y);
                af[mt][3] = __float_as_uint(f1.y);
            }
            uint32_t bf[8][2];
#pragma unroll
            for (int nt = 0; nt < 8; nt++) {
                float2 f = Bs[cur][s][q][wn * 64 + nt * 8 + g];
                bf[nt][0] = __float_as_uint(f.x);
                bf[nt][1] = __float_as_uint(f.y);
            }
#pragma unroll
            for (int mt = 0; mt < 2; mt++)
#pragma unroll
                for (int nt = 0; nt < 8; nt++) {
                    asm volatile(
                        "mma.sync.aligned.m16n8k8.row.col.f32.tf32.tf32.f32 "
                        "{%0,%1,%2,%3}, {%4,%5,%6,%7}, {%8,%9}, {%0,%1,%2,%3};\n"
                        : "+f"(acc[mt][nt][0]), "+f"(acc[mt][nt][1]),
                          "+f"(acc[mt][nt][2]), "+f"(acc[mt][nt][3])
                        : "r"(af[mt][0]), "r"(af[mt][1]), "r"(af[mt][2]), "r"(af[mt][3]),
                          "r"(bf[nt][0]), "r"(bf[nt][1]));
                }
        }

        if (kt + 1 < ntiles) store_tile((kt + 1) & 1);
        __syncthreads();
    }

    // ---- epilogue ----
    const bool has_bias = flags & 1;
    const bool do_relu  = flags & 2;
    const int remap     = (flags >> 2) & 3;

#pragma unroll
    for (int mt = 0; mt < 2; mt++) {
#pragma unroll
        for (int half = 0; half < 2; half++) {
            int row = m0 + wm * 32 + mt * 16 + g + half * 8;
            if (row >= M) continue;
            int out_row = row;
            if (remap == 1)      { int t = row % TT, b = row / TT; out_row = t * BB + b; }
            else if (remap == 2) { int t = row / BB, b = row % BB; out_row = b * TT + t; }
            float* crow = &Cz[(size_t)out_row * N];
            float* c2row = C2 ? &C2[(size_t)out_row * N] : nullptr;
#pragma unroll
            for (int nt = 0; nt < 8; nt++) {
#pragma unroll
                for (int cc = 0; cc < 2; cc++) {
                    int col = n0 + wn * 64 + nt * 8 + 2 * q + cc;
                    if (col >= N) continue;
                    float v = acc[mt][nt][half * 2 + cc];
                    if (has_bias) v += bias[col];
                    if (do_relu) v = fmaxf(v, 0.0f);
                    crow[col] = v;
                    if (c2row) c2row[col] = f2tf32f(v);
                }
            }
        }
    }
}

// ---------------------------------------------------------------------------
// SRU scan: sums split-K partials, recurrence + highway.
// Writes exact h_out (highway) AND tf32-rounded h_out_t (next GEMM A).
// ---------------------------------------------------------------------------
__global__ void sru_scan_kernel(const float* __restrict__ U0,
                                const float* __restrict__ U1,
                                const float* __restrict__ h_in,
                                const float* __restrict__ c0,
                                const float* __restrict__ b_lay,
                                float* __restrict__ h_out,
                                float* __restrict__ h_out_t,
                                float* __restrict__ c_out)
{
    int idx = blockIdx.x * blockDim.x + threadIdx.x;
    if (idx >= BB * HH) return;
    int b = idx / HH;
    int j = idx % HH;

    float c = c0[(size_t)b * HH + j];
    const float bf = b_lay[j];
    const float br = b_lay[HH + j];

    size_t base = (size_t)b * (3 * HH);
    float xt = U0[base + j]          + U1[base + j];
    float uf = U0[base + HH + j]     + U1[base + HH + j];
    float ur = U0[base + 2 * HH + j] + U1[base + 2 * HH + j];
    float hp = h_in[(size_t)b * HH + j];

#pragma unroll
    for (int t = 0; t < TT; t++) {
        float nxt = 0.f, nuf = 0.f, nur = 0.f, nhp = 0.f;
        if (t + 1 < TT) {
            int r = (t + 1) * BB + b;
            size_t nb = (size_t)r * (3 * HH);
            nxt = U0[nb + j]          + U1[nb + j];
            nuf = U0[nb + HH + j]     + U1[nb + HH + j];
            nur = U0[nb + 2 * HH + j] + U1[nb + 2 * HH + j];
            nhp = h_in[(size_t)r * HH + j];
        }
        float f  = 1.0f / (1.0f + __expf(-(uf + bf)));
        float rr = 1.0f / (1.0f + __expf(-(ur + br)));
        c = f * c + (1.0f - f) * xt;
        int r = t * BB + b;
        float hv = rr * tanhf(c) + (1.0f - rr) * hp;
        h_out[(size_t)r * HH + j] = hv;
        h_out_t[(size_t)r * HH + j] = f2tf32f(hv);
        xt = nxt; uf = nuf; ur = nur; hp = nhp;
    }
    c_out[(size_t)b * HH + j] = c;
}

// ---------------------------------------------------------------------------
// Combine split-K partials. mode 0: write rounded (GEMM A input, dense3).
// mode 2 (remap tB->bT): write exact (final out, dense4).
// ---------------------------------------------------------------------------
__global__ void combine_kernel(const float* __restrict__ p0,
                               const float* __restrict__ p1,
                               const float* __restrict__ bias,
                               float* __restrict__ C, int N, int flags)
{
    int idx = blockIdx.x * blockDim.x + threadIdx.x;
    if (idx >= ROWS * N) return;
    int row = idx / N;
    int col = idx - row * N;
    float v = p0[idx] + p1[idx];
    if (flags & 1) v += bias[col];
    if (flags & 2) v = fmaxf(v, 0.0f);
    int orow = row;
    if (((flags >> 2) & 3) == 2) { int t = row / BB, b = row % BB; orow = b * TT + t; }
    if (flags & 32) v = f2tf32f(v);   // round for GEMM consumption
    C[(size_t)orow * N + col] = v;
}

// ---------------------------------------------------------------------------

extern "C" void kernel_launch(void* const* d_in, const int* in_sizes, int n_in,
                              void* d_out, int out_size)
{
    const float* x      = (const float*)d_in[0];
    const float* hidden = (const float*)d_in[1];
    const float* W1     = (const float*)d_in[2];
    const float* b1     = (const float*)d_in[3];
    const float* sruW   = (const float*)d_in[4];
    const float* srub   = (const float*)d_in[5];
    const float* W3     = (const float*)d_in[6];
    const float* b3     = (const float*)d_in[7];
    const float* W4     = (const float*)d_in[8];
    const float* b4     = (const float*)d_in[9];
    float* out = (float*)d_out;

    float *hbuf0, *hbuf1, *ht0, *ht1, *Ubuf, *cdump, *hrelut;
    float *xt, *w1t, *wst, *w3t, *w4t;
    cudaGetSymbolAddress((void**)&hbuf0, g_h);      hbuf1 = hbuf0 + (size_t)ROWS * HH;
    cudaGetSymbolAddress((void**)&ht0,   g_ht);     ht1   = ht0   + (size_t)ROWS * HH;
    cudaGetSymbolAddress((void**)&Ubuf,  g_U);
    cudaGetSymbolAddress((void**)&cdump, g_cdump);
    cudaGetSymbolAddress((void**)&hrelut, g_hrelu_t);
    cudaGetSymbolAddress((void**)&xt,  g_xt);
    cudaGetSymbolAddress((void**)&w1t, g_w1t);
    cudaGetSymbolAddress((void**)&wst, g_wst);
    cudaGetSymbolAddress((void**)&w3t, g_w3t);
    cudaGetSymbolAddress((void**)&w4t, g_w4t);
    const int SLAB = ROWS * 3 * HH;
    float* Ubuf1 = Ubuf + SLAB;

    const int total_out = ROWS * OUTD + LL * BB * HH;
    const bool write_hidden = (out_size >= total_out);
    float* hid_out_base = write_hidden ? (out + (size_t)ROWS * OUTD) : nullptr;

    // 0) one-time tf32 rounding of static operands
    {
        auto rc = [&](const float* s, float* d, int n) {
            round_copy4<<<(n / 4 + 255) / 256, 256>>>((const float4*)s, (float4*)d, n / 4);
        };
        rc(x,    xt,  ROWS * FEA);
        rc(W1,   w1t, FEA * HH);
        rc(sruW, wst, LL * HH * 3 * HH);
        rc(W3,   w3t, HH * HH);
        round_pad_w4<<<(HH * W4LD + 255) / 256, 256>>>(W4, w4t);
    }

    // 1) dense1: xt @ w1t -> exact h0 + rounded twin (time-major)
    tf32gemm_kernel<<<dim3(HH / GBN, (ROWS + GBM - 1) / GBM, 1), 128>>>(
        xt, w1t, b1, hbuf0, ht0, ROWS, HH, FEA, HH, FEA, 0, 1 | (1 << 2));

    // 2) SRU layers
    float* bufs[2]  = {hbuf0, hbuf1};
    float* tbufs[2] = {ht0, ht1};
    for (int l = 0; l < LL; l++) {
        const float* hin   = bufs[l & 1];
        const float* hint  = tbufs[l & 1];
        float*       hout  = bufs[(l + 1) & 1];
        float*       houtt = tbufs[(l + 1) & 1];
        const float* Wl = wst + (size_t)l * HH * 3 * HH;
        const float* bl = srub + (size_t)l * 2 * HH;
        const float* c0 = hidden + (size_t)l * BB * HH;
        float* cout = write_hidden ? (hid_out_base + (size_t)l * BB * HH) : cdump;

        tf32gemm_kernel<<<dim3(3 * HH / GBN, (ROWS + GBM - 1) / GBM, 2), 128>>>(
            hint, Wl, nullptr, Ubuf, nullptr, ROWS, 3 * HH, HH, 3 * HH, HH / 2, SLAB, 0);
        sru_scan_kernel<<<(BB * HH + 255) / 256, 256>>>(Ubuf, Ubuf1, hin, c0, bl,
                                                        hout, houtt, cout);
    }
    float* hfint = tbufs[LL & 1];

    // 3) dense3 (split-K=2) + combine(bias, relu, round -> dense4 A)
    tf32gemm_kernel<<<dim3(HH / GBN, (ROWS + GBM - 1) / GBM, 2), 128>>>(
        hfint, w3t, nullptr, Ubuf, nullptr, ROWS, HH, HH, HH, HH / 2, SLAB, 0);
    combine_kernel<<<(ROWS * HH + 255) / 256, 256>>>(Ubuf, Ubuf1, b3, hrelut, HH, 3 | 32);

    // 4) dense4 (split-K=2, padded W4) + combine(bias, remap to batch-major, exact)
    tf32gemm_kernel<<<dim3((OUTD + GBN - 1) / GBN, (ROWS + GBM - 1) / GBM, 2), 128>>>(
        hrelut, w4t, nullptr, Ubuf, nullptr, ROWS, OUTD, HH, W4LD, HH / 2, SLAB, 0);
    combine_kernel<<<(ROWS * OUTD + 255) / 256, 256>>>(Ubuf, Ubuf1, b4, out, OUTD, 1 | (2 << 2));
}

// round 17
// speedup vs baseline: 3.9336x; 1.0040x over previous
#include <cuda_runtime.h>
#include <cuda_bf16.h>
#include <math.h>
#include <stdint.h>

// Problem constants
#define BB 40
#define TT 20
#define FEA 200
#define HH 1024
#define OUTD 1095
#define LL 12
#define ROWS (BB*TT)   // 800
#define W4LD 1096      // padded row stride for W4 tf32 copy

// Scratch (device globals; no allocation allowed)
__device__ float g_h[2][ROWS * HH];        // exact activations (highway path)
__device__ float g_ht[2][ROWS * HH];       // tf32-rounded twins (GEMM A operands)
__device__ float g_U[2][ROWS * 3 * HH];    // split-K partial buffers
__device__ float g_hrelu_t[ROWS * HH];     // rounded dense3 output (dense4 A)
__device__ float g_cdump[BB * HH];
// tf32-rounded static operands
__device__ float g_xt[ROWS * FEA];
__device__ float g_w1t[FEA * HH];
__device__ float g_wst[LL * HH * 3 * HH];
__device__ float g_w3t[HH * HH];
__device__ float g_w4t[HH * W4LD + 256];   // padded + slack for tile overreach

__device__ __forceinline__ float f2tf32f(float x) {
    uint32_t r;
    asm("cvt.rna.tf32.f32 %0, %1;" : "=r"(r) : "f"(x));
    return __uint_as_float(r);
}

// ---------------------------------------------------------------------------
// One-time conversions (per launch).
// ---------------------------------------------------------------------------
__global__ void round_copy4(const float4* __restrict__ src, float4* __restrict__ dst, int n4)
{
    int i = blockIdx.x * blockDim.x + threadIdx.x;
    if (i >= n4) return;
    float4 v = src[i];
    dst[i] = make_float4(f2tf32f(v.x), f2tf32f(v.y), f2tf32f(v.z), f2tf32f(v.w));
}
__global__ void round_pad_w4(const float* __restrict__ src, float* __restrict__ dst)
{
    int i = blockIdx.x * blockDim.x + threadIdx.x;   // over HH*W4LD
    if (i >= HH * W4LD) return;
    int k = i / W4LD, n = i - k * W4LD;
    dst[i] = (n < OUTD) ? f2tf32f(src[(size_t)k * OUTD + n]) : 0.0f;
}

// ---------------------------------------------------------------------------
// TF32 tensor-core GEMM (mma.sync m16n8k8), CTA 64x128, BK=16, 4 warps 2x2.
// Pre-rounded operands; templated FAST path drops all staging predicates,
// pointer-bump addressing, A staging via 4x STS.64.
// flags: bit0 bias, bit1 relu, bits[2:4] remap (1: bT->tB, 2: tB->bT)
// ---------------------------------------------------------------------------
#define GBM 64
#define GBN 128
#define GBK 16
#define APS 68
#define BPS 132

template<bool FAST>
__device__ __forceinline__ void gemm_run(
    const float* __restrict__ A, const float* __restrict__ B,
    const float* __restrict__ bias, float* __restrict__ Cz, float* __restrict__ C2,
    int M, int N, int K, int ldb, int k0, int k1, int m0, int n0, int flags,
    float2 (*As)[2][4][APS], float2 (*Bs)[2][4][BPS])
{
    const int tid  = threadIdx.x;
    const int lane = tid & 31;
    const int warp = tid >> 5;
    const int wm = warp >> 1;
    const int wn = warp & 1;
    const int q = lane & 3;
    const int g = lane >> 2;

    float acc[2][8][4];
#pragma unroll
    for (int mt = 0; mt < 2; mt++)
#pragma unroll
        for (int nt = 0; nt < 8; nt++)
#pragma unroll
            for (int e = 0; e < 4; e++) acc[mt][nt][e] = 0.0f;

    const int ntiles = (k1 - k0 + GBK - 1) / GBK;

    // A staging: row = tid>>1, k-half sA=(tid&1)  -> 8 consecutive k
    const int aRow = tid >> 1;
    const int sA   = tid & 1;
    const bool aValid = FAST || ((m0 + aRow) < M);
    const float* aPtr = A + (size_t)(aValid ? (m0 + aRow) : 0) * K + k0 + sA * 8;

    // B staging: 2 units -> 2 rows x float4 each
    int ssU[2], qqU[2], nqU[2];
    const float* bPtr[2][2];
#pragma unroll
    for (int u = 0; u < 2; u++) {
        int unit = tid + u * 128;
        int p = unit >> 5;
        nqU[u] = unit & 31;
        ssU[u] = p >> 2;
        qqU[u] = p & 3;
        int gn = n0 + nqU[u] * 4;
#pragma unroll
        for (int rr = 0; rr < 2; rr++) {
            int roff = ssU[u] * 8 + qqU[u] + rr * 4;
            bPtr[u][rr] = B + (size_t)(k0 + roff) * ldb + gn;
        }
    }

    float4 aS[2];
    float4 bS[2][2];

    auto load_tile = [&](int kt) {
        if (FAST) {
            aS[0] = *reinterpret_cast<const float4*>(aPtr);
            aS[1] = *reinterpret_cast<const float4*>(aPtr + 4);
            aPtr += GBK;
#pragma unroll
            for (int u = 0; u < 2; u++)
#pragma unroll
                for (int rr = 0; rr < 2; rr++) {
                    bS[u][rr] = *reinterpret_cast<const float4*>(bPtr[u][rr]);
                    bPtr[u][rr] += (size_t)GBK * ldb;
                }
        } else {
            const int kk = k0 + kt * GBK;
#pragma unroll
            for (int i = 0; i < 2; i++) {
                int gk = kk + sA * 8 + i * 4;
                if (aValid && gk + 4 <= k1) {
                    aS[i] = *reinterpret_cast<const float4*>(&A[(size_t)(m0 + aRow) * K + gk]);
                } else if (aValid && gk < k1) {
                    float t[4];
#pragma unroll
                    for (int c = 0; c < 4; c++)
                        t[c] = (gk + c < k1) ? A[(size_t)(m0 + aRow) * K + gk + c] : 0.f;
                    aS[i] = make_float4(t[0], t[1], t[2], t[3]);
                } else {
                    aS[i] = make_float4(0.f, 0.f, 0.f, 0.f);
                }
            }
#pragma unroll
            for (int u = 0; u < 2; u++)
#pragma unroll
                for (int rr = 0; rr < 2; rr++) {
                    int gk = kk + ssU[u] * 8 + qqU[u] + rr * 4;
                    if (gk < k1) {
                        bS[u][rr] = *reinterpret_cast<const float4*>(
                            &B[(size_t)gk * ldb + n0 + nqU[u] * 4]);
                    } else {
                        bS[u][rr] = make_float4(0.f, 0.f, 0.f, 0.f);
                    }
                }
        }
    };

    auto store_tile = [&](int buf) {
        // A: 4x STS.64 of (k, k+4) pairs
        const float a0[4] = {aS[0].x, aS[0].y, aS[0].z, aS[0].w};
        const float a1[4] = {aS[1].x, aS[1].y, aS[1].z, aS[1].w};
#pragma unroll
        for (int c = 0; c < 4; c++)
            As[buf][sA][c][aRow] = make_float2(a0[c], a1[c]);
        // B: 2x STS.128 per unit, packed (kq, kq+4) pairs
#pragma unroll
        for (int u = 0; u < 2; u++) {
            float4 s0 = make_float4(bS[u][0].x, bS[u][1].x, bS[u][0].y, bS[u][1].y);
            float4 s1 = make_float4(bS[u][0].z, bS[u][1].z, bS[u][0].w, bS[u][1].w);
            float4* base = reinterpret_cast<float4*>(&Bs[buf][ssU[u]][qqU[u]][nqU[u] * 4]);
            base[0] = s0;
            base[1] = s1;
        }
    };

    load_tile(0);
    store_tile(0);
    __syncthreads();

    for (int kt = 0; kt < ntiles; kt++) {
        int cur = kt & 1;
        if (kt + 1 < ntiles) load_tile(kt + 1);

#pragma unroll
        for (int s = 0; s < 2; s++) {
            uint32_t af[2][4];
#pragma unroll
            for (int mt = 0; mt < 2; mt++) {
                int mo = wm * 32 + mt * 16;
                float2 f0 = As[cur][s][q][mo + g];
                float2 f1 = As[cur][s][q][mo + g + 8];
                af[mt][0] = __float_as_uint(f0.x);
                af[mt][1] = __float_as_uint(f1.x);
                af[mt][2] = __float_as_uint(f0.y);
                af[mt][3] = __float_as_uint(f1.y);
            }
            uint32_t bf[8][2];
#pragma unroll
            for (int nt = 0; nt < 8; nt++) {
                float2 f = Bs[cur][s][q][wn * 64 + nt * 8 + g];
                bf[nt][0] = __float_as_uint(f.x);
                bf[nt][1] = __float_as_uint(f.y);
            }
#pragma unroll
            for (int mt = 0; mt < 2; mt++)
#pragma unroll
                for (int nt = 0; nt < 8; nt++) {
                    asm volatile(
                        "mma.sync.aligned.m16n8k8.row.col.f32.tf32.tf32.f32 "
                        "{%0,%1,%2,%3}, {%4,%5,%6,%7}, {%8,%9}, {%0,%1,%2,%3};\n"
                        : "+f"(acc[mt][nt][0]), "+f"(acc[mt][nt][1]),
                          "+f"(acc[mt][nt][2]), "+f"(acc[mt][nt][3])
                        : "r"(af[mt][0]), "r"(af[mt][1]), "r"(af[mt][2]), "r"(af[mt][3]),
                          "r"(bf[nt][0]), "r"(bf[nt][1]));
                }
        }

        if (kt + 1 < ntiles) store_tile((kt + 1) & 1);
        __syncthreads();
    }

    // ---- epilogue ----
    const bool has_bias = flags & 1;
    const bool do_relu  = flags & 2;
    const int remap     = (flags >> 2) & 3;

#pragma unroll
    for (int mt = 0; mt < 2; mt++) {
#pragma unroll
        for (int half = 0; half < 2; half++) {
            int row = m0 + wm * 32 + mt * 16 + g + half * 8;
            if (row >= M) continue;
            int out_row = row;
            if (remap == 1)      { int t = row % TT, b = row / TT; out_row = t * BB + b; }
            else if (remap == 2) { int t = row / BB, b = row % BB; out_row = b * TT + t; }
            float* crow = &Cz[(size_t)out_row * N];
            float* c2row = C2 ? &C2[(size_t)out_row * N] : nullptr;
#pragma unroll
            for (int nt = 0; nt < 8; nt++) {
#pragma unroll
                for (int cc = 0; cc < 2; cc++) {
                    int col = n0 + wn * 64 + nt * 8 + 2 * q + cc;
                    if (col >= N) continue;
                    float v = acc[mt][nt][half * 2 + cc];
                    if (has_bias) v += bias[col];
                    if (do_relu) v = fmaxf(v, 0.0f);
                    crow[col] = v;
                    if (c2row) c2row[col] = f2tf32f(v);
                }
            }
        }
    }
}

__global__ __launch_bounds__(128, 3)
void tf32gemm_kernel(const float* __restrict__ A, const float* __restrict__ B,
                     const float* __restrict__ bias, float* __restrict__ C,
                     float* __restrict__ C2,
                     int M, int N, int K, int ldb, int koff_per_z, int partStride, int flags)
{
    __shared__ float2 As[2][2][4][APS];
    __shared__ float2 Bs[2][2][4][BPS];

    const int m0 = blockIdx.y * GBM;
    const int n0 = blockIdx.x * GBN;
    const int k0 = blockIdx.z * koff_per_z;
    const int k1 = (k0 + koff_per_z < K) ? (k0 + koff_per_z) : K;
    float* Cz = C + (size_t)blockIdx.z * partStride;

    const bool fast = (m0 + GBM <= M) && (((k1 - k0) & (GBK - 1)) == 0);
    if (fast)
        gemm_run<true >(A, B, bias, Cz, C2, M, N, K, ldb, k0, k1, m0, n0, flags, As, Bs);
    else
        gemm_run<false>(A, B, bias, Cz, C2, M, N, K, ldb, k0, k1, m0, n0, flags, As, Bs);
}

// ---------------------------------------------------------------------------
// SRU scan: sums split-K partials, recurrence + highway.
// ---------------------------------------------------------------------------
__global__ void sru_scan_kernel(const float* __restrict__ U0,
                                const float* __restrict__ U1,
                                const float* __restrict__ h_in,
                                const float* __restrict__ c0,
                                const float* __restrict__ b_lay,
                                float* __restrict__ h_out,
                                float* __restrict__ h_out_t,
                                float* __restrict__ c_out)
{
    int idx = blockIdx.x * blockDim.x + threadIdx.x;
    if (idx >= BB * HH) return;
    int b = idx / HH;
    int j = idx % HH;

    float c = c0[(size_t)b * HH + j];
    const float bf = b_lay[j];
    const float br = b_lay[HH + j];

    size_t base = (size_t)b * (3 * HH);
    float xt = U0[base + j]          + U1[base + j];
    float uf = U0[base + HH + j]     + U1[base + HH + j];
    float ur = U0[base + 2 * HH + j] + U1[base + 2 * HH + j];
    float hp = h_in[(size_t)b * HH + j];

#pragma unroll
    for (int t = 0; t < TT; t++) {
        float nxt = 0.f, nuf = 0.f, nur = 0.f, nhp = 0.f;
        if (t + 1 < TT) {
            int r = (t + 1) * BB + b;
            size_t nb = (size_t)r * (3 * HH);
            nxt = U0[nb + j]          + U1[nb + j];
            nuf = U0[nb + HH + j]     + U1[nb + HH + j];
            nur = U0[nb + 2 * HH + j] + U1[nb + 2 * HH + j];
            nhp = h_in[(size_t)r * HH + j];
        }
        float f  = 1.0f / (1.0f + __expf(-(uf + bf)));
        float rr = 1.0f / (1.0f + __expf(-(ur + br)));
        c = f * c + (1.0f - f) * xt;
        int r = t * BB + b;
        float hv = rr * tanhf(c) + (1.0f - rr) * hp;
        h_out[(size_t)r * HH + j] = hv;
        h_out_t[(size_t)r * HH + j] = f2tf32f(hv);
        xt = nxt; uf = nuf; ur = nur; hp = nhp;
    }
    c_out[(size_t)b * HH + j] = c;
}

// ---------------------------------------------------------------------------
// Combine split-K partials. flag 32: write tf32-rounded (GEMM A consumption).
// ---------------------------------------------------------------------------
__global__ void combine_kernel(const float* __restrict__ p0,
                               const float* __restrict__ p1,
                               const float* __restrict__ bias,
                               float* __restrict__ C, int N, int flags)
{
    int idx = blockIdx.x * blockDim.x + threadIdx.x;
    if (idx >= ROWS * N) return;
    int row = idx / N;
    int col = idx - row * N;
    float v = p0[idx] + p1[idx];
    if (flags & 1) v += bias[col];
    if (flags & 2) v = fmaxf(v, 0.0f);
    int orow = row;
    if (((flags >> 2) & 3) == 2) { int t = row / BB, b = row % BB; orow = b * TT + t; }
    if (flags & 32) v = f2tf32f(v);
    C[(size_t)orow * N + col] = v;
}

// ---------------------------------------------------------------------------

extern "C" void kernel_launch(void* const* d_in, const int* in_sizes, int n_in,
                              void* d_out, int out_size)
{
    const float* x      = (const float*)d_in[0];
    const float* hidden = (const float*)d_in[1];
    const float* W1     = (const float*)d_in[2];
    const float* b1     = (const float*)d_in[3];
    const float* sruW   = (const float*)d_in[4];
    const float* srub   = (const float*)d_in[5];
    const float* W3     = (const float*)d_in[6];
    const float* b3     = (const float*)d_in[7];
    const float* W4     = (const float*)d_in[8];
    const float* b4     = (const float*)d_in[9];
    float* out = (float*)d_out;

    float *hbuf0, *hbuf1, *ht0, *ht1, *Ubuf, *cdump, *hrelut;
    float *xt, *w1t, *wst, *w3t, *w4t;
    cudaGetSymbolAddress((void**)&hbuf0, g_h);      hbuf1 = hbuf0 + (size_t)ROWS * HH;
    cudaGetSymbolAddress((void**)&ht0,   g_ht);     ht1   = ht0   + (size_t)ROWS * HH;
    cudaGetSymbolAddress((void**)&Ubuf,  g_U);
    cudaGetSymbolAddress((void**)&cdump, g_cdump);
    cudaGetSymbolAddress((void**)&hrelut, g_hrelu_t);
    cudaGetSymbolAddress((void**)&xt,  g_xt);
    cudaGetSymbolAddress((void**)&w1t, g_w1t);
    cudaGetSymbolAddress((void**)&wst, g_wst);
    cudaGetSymbolAddress((void**)&w3t, g_w3t);
    cudaGetSymbolAddress((void**)&w4t, g_w4t);
    const int SLAB = ROWS * 3 * HH;
    float* Ubuf1 = Ubuf + SLAB;

    const int total_out = ROWS * OUTD + LL * BB * HH;
    const bool write_hidden = (out_size >= total_out);
    float* hid_out_base = write_hidden ? (out + (size_t)ROWS * OUTD) : nullptr;

    // 0) one-time tf32 rounding of static operands
    {
        auto rc = [&](const float* s, float* d, int n) {
            round_copy4<<<(n / 4 + 255) / 256, 256>>>((const float4*)s, (float4*)d, n / 4);
        };
        rc(x,    xt,  ROWS * FEA);
        rc(W1,   w1t, FEA * HH);
        rc(sruW, wst, LL * HH * 3 * HH);
        rc(W3,   w3t, HH * HH);
        round_pad_w4<<<(HH * W4LD + 255) / 256, 256>>>(W4, w4t);
    }

    // 1) dense1: xt @ w1t -> exact h0 + rounded twin (time-major)
    tf32gemm_kernel<<<dim3(HH / GBN, (ROWS + GBM - 1) / GBM, 1), 128>>>(
        xt, w1t, b1, hbuf0, ht0, ROWS, HH, FEA, HH, FEA, 0, 1 | (1 << 2));

    // 2) SRU layers
    float* bufs[2]  = {hbuf0, hbuf1};
    float* tbufs[2] = {ht0, ht1};
    for (int l = 0; l < LL; l++) {
        const float* hin   = bufs[l & 1];
        const float* hint  = tbufs[l & 1];
        float*       hout  = bufs[(l + 1) & 1];
        float*       houtt = tbufs[(l + 1) & 1];
        const float* Wl = wst + (size_t)l * HH * 3 * HH;
        const float* bl = srub + (size_t)l * 2 * HH;
        const float* c0 = hidden + (size_t)l * BB * HH;
        float* cout = write_hidden ? (hid_out_base + (size_t)l * BB * HH) : cdump;

        tf32gemm_kernel<<<dim3(3 * HH / GBN, (ROWS + GBM - 1) / GBM, 2), 128>>>(
            hint, Wl, nullptr, Ubuf, nullptr, ROWS, 3 * HH, HH, 3 * HH, HH / 2, SLAB, 0);
        sru_scan_kernel<<<(BB * HH + 255) / 256, 256>>>(Ubuf, Ubuf1, hin, c0, bl,
                                                        hout, houtt, cout);
    }
    float* hfint = tbufs[LL & 1];

    // 3) dense3 (split-K=2) + combine(bias, relu, round -> dense4 A)
    tf32gemm_kernel<<<dim3(HH / GBN, (ROWS + GBM - 1) / GBM, 2), 128>>>(
        hfint, w3t, nullptr, Ubuf, nullptr, ROWS, HH, HH, HH, HH / 2, SLAB, 0);
    combine_kernel<<<(ROWS * HH + 255) / 256, 256>>>(Ubuf, Ubuf1, b3, hrelut, HH, 3 | 32);

    // 4) dense4 (split-K=2, padded W4) + combine(bias, remap to batch-major, exact)
    tf32gemm_kernel<<<dim3((OUTD + GBN - 1) / GBN, (ROWS + GBM - 1) / GBM, 2), 128>>>(
        hrelut, w4t, nullptr, Ubuf, nullptr, ROWS, OUTD, HH, W4LD, HH / 2, SLAB, 0);
    combine_kernel<<<(ROWS * OUTD + 255) / 256, 256>>>(Ubuf, Ubuf1, b4, out, OUTD, 1 | (2 << 2));
}